// round 6
// baseline (speedup 1.0000x reference)
#include <cuda_runtime.h>
#include <math.h>

#define NA   768
#define FDIM 128
#define NRBF 32
#define MAXNBR 192

// Physics constants (match reference exactly)
#define CUT2f   25.0f
#define GAMf    40.96f                       /* (32/5)^2 */
#define CSPf    (5.0f/31.0f)                 /* RBF center spacing */
#define KBf     8.617330337217213e-05f
#define KTf     (300.0f*KBf)
#define Q0f     (2.0f*(float)(NA*3)*KTf*400.0f)
#define QCf     (2.0f*KTf*400.0f)
#define TARGETf (0.5f*(float)(NA*3)*KTf)

// Scratch (static __device__ arrays: allocation-free, graph-safe)
__device__ int   g_nbr[NA*MAXNBR];
__device__ int   g_cnt[NA];
__device__ float g_h  [NA*FDIM];
__device__ float g_W2T[FDIM*FDIM];
__device__ float g_W3T[FDIM*FDIM];
__device__ float g_gm [NA*FDIM];     // dE/dm per atom
__device__ float g_gq [NA*3];        // dE/dq accumulator

// ---------------------------------------------------------------------------
// K0: gather h = embed[atomic_numbers], transpose W2, W3
__global__ void k_prep(const float* __restrict__ embed, const int* __restrict__ zat,
                       const float* __restrict__ W2, const float* __restrict__ W3) {
    int b = blockIdx.x, t = threadIdx.x;
    g_h[b*FDIM + t] = embed[zat[b]*FDIM + t];
    if (b < FDIM) {
        g_W2T[b*FDIM + t] = W2[t*FDIM + b];
        g_W3T[b*FDIM + t] = W3[t*FDIM + b];
    }
}

// ---------------------------------------------------------------------------
// K1: cutoff neighbor list (block per atom) + zero force accumulator
__global__ void k_nbr(const float* __restrict__ q) {
    int i = blockIdx.x, t = threadIdx.x;
    __shared__ int cnt;
    if (t == 0) cnt = 0;
    if (t < 3)  g_gq[i*3 + t] = 0.0f;
    __syncthreads();
    float qx = q[3*i], qy = q[3*i+1], qz = q[3*i+2];
    for (int j = t; j < NA; j += blockDim.x) {
        if (j == i) continue;
        float dx = qx - q[3*j], dy = qy - q[3*j+1], dz = qz - q[3*j+2];
        float d2 = dx*dx + dy*dy + dz*dz;
        if (d2 < CUT2f) {
            int p = atomicAdd(&cnt, 1);
            if (p < MAXNBR) g_nbr[i*MAXNBR + p] = j;
        }
    }
    __syncthreads();
    if (t == 0) g_cnt[i] = (cnt < MAXNBR) ? cnt : MAXNBR;
}

// ---------------------------------------------------------------------------
// K2: forward messages m_i, then fused per-atom backward head dE/dm_i
//     block per atom i, 128 threads (thread t = feature)
__global__ void __launch_bounds__(FDIM)
k_fwd(const float* __restrict__ q,
      const float* __restrict__ W1, const float* __restrict__ b1,
      const float* __restrict__ W2, const float* __restrict__ b2,
      const float* __restrict__ W3, const float* __restrict__ w_out) {
    int i = blockIdx.x, t = threadIdx.x;
    __shared__ float srbf[NRBF];
    __shared__ float sA[FDIM];
    __shared__ float sB[FDIM];

    float qx = q[3*i], qy = q[3*i+1], qz = q[3*i+2];
    float b1t = b1[t], b2t = b2[t];
    float m = 0.0f;
    int cnt = g_cnt[i];

    for (int jn = 0; jn < cnt; jn++) {
        int j = g_nbr[i*MAXNBR + jn];
        float dx = qx - q[3*j], dy = qy - q[3*j+1], dz = qz - q[3*j+2];
        float d = sqrtf(dx*dx + dy*dy + dz*dz);

        __syncthreads();                       // protect srbf/sA from prev iter
        if (t < NRBF) {
            float u = d - (float)t * CSPf;
            srbf[t] = __expf(-GAMf * u * u);
        }
        __syncthreads();

        float z = b1t;
        #pragma unroll
        for (int k = 0; k < NRBF; k++) z = fmaf(srbf[k], W1[k*FDIM + t], z);
        sA[t] = fmaxf(z, 0.0f);
        __syncthreads();

        float filt = b2t;
        #pragma unroll 8
        for (int f = 0; f < FDIM; f++) filt = fmaf(sA[f], W2[f*FDIM + t], filt);
        m = fmaf(filt, g_h[j*FDIM + t], m);
    }

    // per-atom head: a = m@W3 ; gm = W3 @ (w_out * 1[a>0])
    __syncthreads();
    sA[t] = m;
    __syncthreads();
    float a = 0.0f;
    #pragma unroll 8
    for (int f = 0; f < FDIM; f++) a = fmaf(sA[f], W3[f*FDIM + t], a);
    sB[t] = (a > 0.0f) ? w_out[t] : 0.0f;
    __syncthreads();
    float gm = 0.0f;
    #pragma unroll 8
    for (int g = 0; g < FDIM; g++) gm = fmaf(sB[g], g_W3T[g*FDIM + t], gm);
    g_gm[i*FDIM + t] = gm;
}

// ---------------------------------------------------------------------------
// K3: backward per pair -> dE/dq scatter. Block per atom i, 128 threads.
__global__ void __launch_bounds__(FDIM)
k_bwd(const float* __restrict__ q,
      const float* __restrict__ W1, const float* __restrict__ b1) {
    int i = blockIdx.x, t = threadIdx.x;
    __shared__ float srbf[NRBF];
    __shared__ float sgf[FDIM];
    __shared__ float sgz[FDIM];

    float qx = q[3*i], qy = q[3*i+1], qz = q[3*i+2];
    float gmf = g_gm[i*FDIM + t];
    float b1t = b1[t];
    float fx = 0.0f, fy = 0.0f, fz = 0.0f;   // dE/dq_i accumulator (lane 0 only)
    int cnt = g_cnt[i];

    for (int jn = 0; jn < cnt; jn++) {
        int j = g_nbr[i*MAXNBR + jn];
        float dx = qx - q[3*j], dy = qy - q[3*j+1], dz = qz - q[3*j+2];
        float d = sqrtf(dx*dx + dy*dy + dz*dz);

        __syncthreads();
        sgf[t] = gmf * g_h[j*FDIM + t];        // dE/dfilt
        if (t < NRBF) {
            float u = d - (float)t * CSPf;
            srbf[t] = __expf(-GAMf * u * u);
        }
        __syncthreads();

        // recompute z for the relu mask, then gz = 1[z>0] * (W2^T @ gfilt)
        float z = b1t;
        #pragma unroll
        for (int k = 0; k < NRBF; k++) z = fmaf(srbf[k], W1[k*FDIM + t], z);
        float gz = 0.0f;
        #pragma unroll 8
        for (int f = 0; f < FDIM; f++) gz = fmaf(sgf[f], g_W2T[f*FDIM + t], gz);
        sgz[t] = (z > 0.0f) ? gz : 0.0f;
        __syncthreads();

        if (t < NRBF) {                        // warp 0: grbf + dE/dd reduction
            float gr = 0.0f;
            #pragma unroll 8
            for (int f = 0; f < FDIM; f++) gr = fmaf(W1[t*FDIM + f], sgz[f], gr);
            float u = d - (float)t * CSPf;
            float term = gr * (-2.0f * GAMf * u) * srbf[t];   // dE/dd partial
            #pragma unroll
            for (int off = 16; off > 0; off >>= 1)
                term += __shfl_down_sync(0xffffffffu, term, off);
            if (t == 0) {
                float s = term / d;            // (dE/dd)/d
                float gx = s*dx, gy = s*dy, gzc = s*dz;
                fx += gx; fy += gy; fz += gzc;                 // dd/dq_i = +disp/d
                atomicAdd(&g_gq[3*j + 0], -gx);                // dd/dq_j = -disp/d
                atomicAdd(&g_gq[3*j + 1], -gy);
                atomicAdd(&g_gq[3*j + 2], -gzc);
            }
        }
    }
    if (t == 0) {
        atomicAdd(&g_gq[3*i + 0], fx);
        atomicAdd(&g_gq[3*i + 1], fy);
        atomicAdd(&g_gq[3*i + 2], fz);
    }
}

// ---------------------------------------------------------------------------
// K4: KE reduction + dvdt + v passthrough + Nose-Hoover chain RHS
__global__ void k_fin(const float* __restrict__ v, const float* __restrict__ mass,
                      const float* __restrict__ p_eta, float* __restrict__ out) {
    __shared__ float red[256];
    int t = threadIdx.x;
    float ke = 0.0f;
    for (int n = t; n < NA; n += 256) {
        float mn = mass[n];
        float v0 = v[3*n], v1 = v[3*n+1], v2 = v[3*n+2];
        ke += mn * (v0*v0 + v1*v1 + v2*v2);
    }
    red[t] = ke;
    __syncthreads();
    for (int off = 128; off > 0; off >>= 1) {
        if (t < off) red[t] += red[t + off];
        __syncthreads();
    }
    float pe0 = p_eta[0];
    for (int idx = t; idx < NA*3; idx += 256) {
        int n = idx / 3;
        float mn = mass[n], vv = v[idx];
        // f = -dE/dq ; coupled = p_eta0 * (m v) / Q0 ; dvdt = (f - coupled)/m
        out[idx]        = (-g_gq[idx] - pe0 * mn * vv / Q0f) / mn;
        out[NA*3 + idx] = vv;
    }
    if (t == 0) {
        float s_ke = 0.5f * red[0];
        float pe1 = p_eta[1], pe2 = p_eta[2], pe3 = p_eta[3];
        out[2*NA*3 + 0] = 2.0f*(s_ke - TARGETf) - pe0*pe1/QCf;
        out[2*NA*3 + 1] = pe0*pe0/Q0f - KTf - pe1*pe2/QCf;
        out[2*NA*3 + 2] = pe1*pe1/QCf - KTf - pe2*pe3/QCf;
        out[2*NA*3 + 3] = pe2*pe2/QCf - KTf;
    }
}

// ---------------------------------------------------------------------------
extern "C" void kernel_launch(void* const* d_in, const int* in_sizes, int n_in,
                              void* d_out, int out_size) {
    const float* v     = (const float*)d_in[0];
    const float* q     = (const float*)d_in[1];
    const float* p_eta = (const float*)d_in[2];
    const float* mass  = (const float*)d_in[3];
    const float* embed = (const float*)d_in[4];
    const float* W1    = (const float*)d_in[5];
    const float* b1    = (const float*)d_in[6];
    const float* W2    = (const float*)d_in[7];
    const float* b2    = (const float*)d_in[8];
    const float* W3    = (const float*)d_in[9];
    const float* w_out = (const float*)d_in[10];
    const int*   zat   = (const int*)d_in[11];
    float* out = (float*)d_out;
    (void)in_sizes; (void)n_in; (void)out_size;

    k_prep<<<NA, FDIM>>>(embed, zat, W2, W3);
    k_nbr <<<NA, 256 >>>(q);
    k_fwd <<<NA, FDIM>>>(q, W1, b1, W2, b2, W3, w_out);
    k_bwd <<<NA, FDIM>>>(q, W1, b1);
    k_fin <<<1,  256 >>>(v, mass, p_eta, out);
}

// round 7
// speedup vs baseline: 1.0025x; 1.0025x over previous
#include <cuda_runtime.h>
#include <math.h>

#define NA   768
#define FDIM 128
#define NRBF 32
#define MAXNBR 192

// Physics constants (match reference exactly)
#define CUT2f   25.0f
#define GAMf    40.96f                       /* (32/5)^2 */
#define CSPf    (5.0f/31.0f)                 /* RBF center spacing */
#define KBf     8.617330337217213e-05f
#define KTf     (300.0f*KBf)
#define Q0f     (2.0f*(float)(NA*3)*KTf*400.0f)
#define QCf     (2.0f*KTf*400.0f)
#define TARGETf (0.5f*(float)(NA*3)*KTf)

// Scratch (static __device__ arrays: allocation-free, graph-safe)
__device__ int   g_nbr[NA*MAXNBR];
__device__ int   g_cnt[NA];
__device__ float g_h  [NA*FDIM];
__device__ float g_W2T[FDIM*FDIM];
__device__ float g_W3T[FDIM*FDIM];
__device__ float g_gm [NA*FDIM];     // dE/dm per atom
__device__ float g_gq [NA*3];        // dE/dq accumulator

// ---------------------------------------------------------------------------
// K0: gather h = embed[atomic_numbers], transpose W2, W3
__global__ void k_prep(const float* __restrict__ embed, const int* __restrict__ zat,
                       const float* __restrict__ W2, const float* __restrict__ W3) {
    int b = blockIdx.x, t = threadIdx.x;
    g_h[b*FDIM + t] = embed[zat[b]*FDIM + t];
    if (b < FDIM) {
        g_W2T[b*FDIM + t] = W2[t*FDIM + b];
        g_W3T[b*FDIM + t] = W3[t*FDIM + b];
    }
}

// ---------------------------------------------------------------------------
// K1: cutoff neighbor list (block per atom) + zero force accumulator
__global__ void k_nbr(const float* __restrict__ q) {
    int i = blockIdx.x, t = threadIdx.x;
    __shared__ int cnt;
    if (t == 0) cnt = 0;
    if (t < 3)  g_gq[i*3 + t] = 0.0f;
    __syncthreads();
    float qx = q[3*i], qy = q[3*i+1], qz = q[3*i+2];
    for (int j = t; j < NA; j += blockDim.x) {
        if (j == i) continue;
        float dx = qx - q[3*j], dy = qy - q[3*j+1], dz = qz - q[3*j+2];
        float d2 = dx*dx + dy*dy + dz*dz;
        if (d2 < CUT2f) {
            int p = atomicAdd(&cnt, 1);
            if (p < MAXNBR) g_nbr[i*MAXNBR + p] = j;
        }
    }
    __syncthreads();
    if (t == 0) g_cnt[i] = (cnt < MAXNBR) ? cnt : MAXNBR;
}

// ---------------------------------------------------------------------------
// K2: forward messages m_i, then fused per-atom backward head dE/dm_i
//     block per atom i, 128 threads (thread t = feature)
__global__ void __launch_bounds__(FDIM)
k_fwd(const float* __restrict__ q,
      const float* __restrict__ W1, const float* __restrict__ b1,
      const float* __restrict__ W2, const float* __restrict__ b2,
      const float* __restrict__ W3, const float* __restrict__ w_out) {
    int i = blockIdx.x, t = threadIdx.x;
    __shared__ float srbf[NRBF];
    __shared__ float sA[FDIM];
    __shared__ float sB[FDIM];

    float qx = q[3*i], qy = q[3*i+1], qz = q[3*i+2];
    float b1t = b1[t], b2t = b2[t];
    float m = 0.0f;
    int cnt = g_cnt[i];

    for (int jn = 0; jn < cnt; jn++) {
        int j = g_nbr[i*MAXNBR + jn];
        float dx = qx - q[3*j], dy = qy - q[3*j+1], dz = qz - q[3*j+2];
        float d = sqrtf(dx*dx + dy*dy + dz*dz);

        __syncthreads();                       // protect srbf/sA from prev iter
        if (t < NRBF) {
            float u = d - (float)t * CSPf;
            srbf[t] = __expf(-GAMf * u * u);
        }
        __syncthreads();

        float z = b1t;
        #pragma unroll
        for (int k = 0; k < NRBF; k++) z = fmaf(srbf[k], W1[k*FDIM + t], z);
        sA[t] = fmaxf(z, 0.0f);
        __syncthreads();

        float filt = b2t;
        #pragma unroll 8
        for (int f = 0; f < FDIM; f++) filt = fmaf(sA[f], W2[f*FDIM + t], filt);
        m = fmaf(filt, g_h[j*FDIM + t], m);
    }

    // per-atom head: a = m@W3 ; gm = W3 @ (w_out * 1[a>0])
    __syncthreads();
    sA[t] = m;
    __syncthreads();
    float a = 0.0f;
    #pragma unroll 8
    for (int f = 0; f < FDIM; f++) a = fmaf(sA[f], W3[f*FDIM + t], a);
    sB[t] = (a > 0.0f) ? w_out[t] : 0.0f;
    __syncthreads();
    float gm = 0.0f;
    #pragma unroll 8
    for (int g = 0; g < FDIM; g++) gm = fmaf(sB[g], g_W3T[g*FDIM + t], gm);
    g_gm[i*FDIM + t] = gm;
}

// ---------------------------------------------------------------------------
// K3: backward per pair -> dE/dq scatter. Block per atom i, 128 threads.
__global__ void __launch_bounds__(FDIM)
k_bwd(const float* __restrict__ q,
      const float* __restrict__ W1, const float* __restrict__ b1) {
    int i = blockIdx.x, t = threadIdx.x;
    __shared__ float srbf[NRBF];
    __shared__ float sgf[FDIM];
    __shared__ float sgz[FDIM];

    float qx = q[3*i], qy = q[3*i+1], qz = q[3*i+2];
    float gmf = g_gm[i*FDIM + t];
    float b1t = b1[t];
    float fx = 0.0f, fy = 0.0f, fz = 0.0f;   // dE/dq_i accumulator (lane 0 only)
    int cnt = g_cnt[i];

    for (int jn = 0; jn < cnt; jn++) {
        int j = g_nbr[i*MAXNBR + jn];
        float dx = qx - q[3*j], dy = qy - q[3*j+1], dz = qz - q[3*j+2];
        float d = sqrtf(dx*dx + dy*dy + dz*dz);

        __syncthreads();
        sgf[t] = gmf * g_h[j*FDIM + t];        // dE/dfilt
        if (t < NRBF) {
            float u = d - (float)t * CSPf;
            srbf[t] = __expf(-GAMf * u * u);
        }
        __syncthreads();

        // recompute z for the relu mask, then gz = 1[z>0] * (W2^T @ gfilt)
        float z = b1t;
        #pragma unroll
        for (int k = 0; k < NRBF; k++) z = fmaf(srbf[k], W1[k*FDIM + t], z);
        float gz = 0.0f;
        #pragma unroll 8
        for (int f = 0; f < FDIM; f++) gz = fmaf(sgf[f], g_W2T[f*FDIM + t], gz);
        sgz[t] = (z > 0.0f) ? gz : 0.0f;
        __syncthreads();

        if (t < NRBF) {                        // warp 0: grbf + dE/dd reduction
            float gr = 0.0f;
            #pragma unroll 8
            for (int f = 0; f < FDIM; f++) gr = fmaf(W1[t*FDIM + f], sgz[f], gr);
            float u = d - (float)t * CSPf;
            float term = gr * (-2.0f * GAMf * u) * srbf[t];   // dE/dd partial
            #pragma unroll
            for (int off = 16; off > 0; off >>= 1)
                term += __shfl_down_sync(0xffffffffu, term, off);
            if (t == 0) {
                float s = term / d;            // (dE/dd)/d
                float gx = s*dx, gy = s*dy, gzc = s*dz;
                fx += gx; fy += gy; fz += gzc;                 // dd/dq_i = +disp/d
                atomicAdd(&g_gq[3*j + 0], -gx);                // dd/dq_j = -disp/d
                atomicAdd(&g_gq[3*j + 1], -gy);
                atomicAdd(&g_gq[3*j + 2], -gzc);
            }
        }
    }
    if (t == 0) {
        atomicAdd(&g_gq[3*i + 0], fx);
        atomicAdd(&g_gq[3*i + 1], fy);
        atomicAdd(&g_gq[3*i + 2], fz);
    }
}

// ---------------------------------------------------------------------------
// K4: KE reduction + dvdt + v passthrough + Nose-Hoover chain RHS
__global__ void k_fin(const float* __restrict__ v, const float* __restrict__ mass,
                      const float* __restrict__ p_eta, float* __restrict__ out) {
    __shared__ float red[256];
    int t = threadIdx.x;
    float ke = 0.0f;
    for (int n = t; n < NA; n += 256) {
        float mn = mass[n];
        float v0 = v[3*n], v1 = v[3*n+1], v2 = v[3*n+2];
        ke += mn * (v0*v0 + v1*v1 + v2*v2);
    }
    red[t] = ke;
    __syncthreads();
    for (int off = 128; off > 0; off >>= 1) {
        if (t < off) red[t] += red[t + off];
        __syncthreads();
    }
    float pe0 = p_eta[0];
    for (int idx = t; idx < NA*3; idx += 256) {
        int n = idx / 3;
        float mn = mass[n], vv = v[idx];
        // f = -dE/dq ; coupled = p_eta0 * (m v) / Q0 ; dvdt = (f - coupled)/m
        out[idx]        = (-g_gq[idx] - pe0 * mn * vv / Q0f) / mn;
        out[NA*3 + idx] = vv;
    }
    if (t == 0) {
        float s_ke = 0.5f * red[0];
        float pe1 = p_eta[1], pe2 = p_eta[2], pe3 = p_eta[3];
        out[2*NA*3 + 0] = 2.0f*(s_ke - TARGETf) - pe0*pe1/QCf;
        out[2*NA*3 + 1] = pe0*pe0/Q0f - KTf - pe1*pe2/QCf;
        out[2*NA*3 + 2] = pe1*pe1/QCf - KTf - pe2*pe3/QCf;
        out[2*NA*3 + 3] = pe2*pe2/QCf - KTf;
    }
}

// ---------------------------------------------------------------------------
extern "C" void kernel_launch(void* const* d_in, const int* in_sizes, int n_in,
                              void* d_out, int out_size) {
    const float* v     = (const float*)d_in[0];
    const float* q     = (const float*)d_in[1];
    const float* p_eta = (const float*)d_in[2];
    const float* mass  = (const float*)d_in[3];
    const float* embed = (const float*)d_in[4];
    const float* W1    = (const float*)d_in[5];
    const float* b1    = (const float*)d_in[6];
    const float* W2    = (const float*)d_in[7];
    const float* b2    = (const float*)d_in[8];
    const float* W3    = (const float*)d_in[9];
    const float* w_out = (const float*)d_in[10];
    const int*   zat   = (const int*)d_in[11];
    float* out = (float*)d_out;
    (void)in_sizes; (void)n_in; (void)out_size;

    k_prep<<<NA, FDIM>>>(embed, zat, W2, W3);
    k_nbr <<<NA, 256 >>>(q);
    k_fwd <<<NA, FDIM>>>(q, W1, b1, W2, b2, W3, w_out);
    k_bwd <<<NA, FDIM>>>(q, W1, b1);
    k_fin <<<1,  256 >>>(v, mass, p_eta, out);
}

// round 8
// speedup vs baseline: 1.0037x; 1.0012x over previous
#include <cuda_runtime.h>
#include <math.h>

#define NA   768
#define FDIM 128
#define NRBF 32
#define MAXNBR 192

// Physics constants (match reference exactly)
#define CUT2f   25.0f
#define GAMf    40.96f                       /* (32/5)^2 */
#define CSPf    (5.0f/31.0f)                 /* RBF center spacing */
#define KBf     8.617330337217213e-05f
#define KTf     (300.0f*KBf)
#define Q0f     (2.0f*(float)(NA*3)*KTf*400.0f)
#define QCf     (2.0f*KTf*400.0f)
#define TARGETf (0.5f*(float)(NA*3)*KTf)

// Scratch (static __device__ arrays: allocation-free, graph-safe)
__device__ int   g_nbr[NA*MAXNBR];
__device__ int   g_cnt[NA];
__device__ float g_h  [NA*FDIM];
__device__ float g_W2T[FDIM*FDIM];
__device__ float g_W3T[FDIM*FDIM];
__device__ float g_gm [NA*FDIM];     // dE/dm per atom
__device__ float g_gq [NA*3];        // dE/dq accumulator

// ---------------------------------------------------------------------------
// K0: gather h = embed[atomic_numbers], transpose W2, W3
__global__ void k_prep(const float* __restrict__ embed, const int* __restrict__ zat,
                       const float* __restrict__ W2, const float* __restrict__ W3) {
    int b = blockIdx.x, t = threadIdx.x;
    g_h[b*FDIM + t] = embed[zat[b]*FDIM + t];
    if (b < FDIM) {
        g_W2T[b*FDIM + t] = W2[t*FDIM + b];
        g_W3T[b*FDIM + t] = W3[t*FDIM + b];
    }
}

// ---------------------------------------------------------------------------
// K1: cutoff neighbor list (block per atom) + zero force accumulator
__global__ void k_nbr(const float* __restrict__ q) {
    int i = blockIdx.x, t = threadIdx.x;
    __shared__ int cnt;
    if (t == 0) cnt = 0;
    if (t < 3)  g_gq[i*3 + t] = 0.0f;
    __syncthreads();
    float qx = q[3*i], qy = q[3*i+1], qz = q[3*i+2];
    for (int j = t; j < NA; j += blockDim.x) {
        if (j == i) continue;
        float dx = qx - q[3*j], dy = qy - q[3*j+1], dz = qz - q[3*j+2];
        float d2 = dx*dx + dy*dy + dz*dz;
        if (d2 < CUT2f) {
            int p = atomicAdd(&cnt, 1);
            if (p < MAXNBR) g_nbr[i*MAXNBR + p] = j;
        }
    }
    __syncthreads();
    if (t == 0) g_cnt[i] = (cnt < MAXNBR) ? cnt : MAXNBR;
}

// ---------------------------------------------------------------------------
// K2: forward messages m_i, then fused per-atom backward head dE/dm_i
//     block per atom i, 128 threads (thread t = feature)
__global__ void __launch_bounds__(FDIM)
k_fwd(const float* __restrict__ q,
      const float* __restrict__ W1, const float* __restrict__ b1,
      const float* __restrict__ W2, const float* __restrict__ b2,
      const float* __restrict__ W3, const float* __restrict__ w_out) {
    int i = blockIdx.x, t = threadIdx.x;
    __shared__ float srbf[NRBF];
    __shared__ float sA[FDIM];
    __shared__ float sB[FDIM];

    float qx = q[3*i], qy = q[3*i+1], qz = q[3*i+2];
    float b1t = b1[t], b2t = b2[t];
    float m = 0.0f;
    int cnt = g_cnt[i];

    for (int jn = 0; jn < cnt; jn++) {
        int j = g_nbr[i*MAXNBR + jn];
        float dx = qx - q[3*j], dy = qy - q[3*j+1], dz = qz - q[3*j+2];
        float d = sqrtf(dx*dx + dy*dy + dz*dz);

        __syncthreads();                       // protect srbf/sA from prev iter
        if (t < NRBF) {
            float u = d - (float)t * CSPf;
            srbf[t] = __expf(-GAMf * u * u);
        }
        __syncthreads();

        float z = b1t;
        #pragma unroll
        for (int k = 0; k < NRBF; k++) z = fmaf(srbf[k], W1[k*FDIM + t], z);
        sA[t] = fmaxf(z, 0.0f);
        __syncthreads();

        float filt = b2t;
        #pragma unroll 8
        for (int f = 0; f < FDIM; f++) filt = fmaf(sA[f], W2[f*FDIM + t], filt);
        m = fmaf(filt, g_h[j*FDIM + t], m);
    }

    // per-atom head: a = m@W3 ; gm = W3 @ (w_out * 1[a>0])
    __syncthreads();
    sA[t] = m;
    __syncthreads();
    float a = 0.0f;
    #pragma unroll 8
    for (int f = 0; f < FDIM; f++) a = fmaf(sA[f], W3[f*FDIM + t], a);
    sB[t] = (a > 0.0f) ? w_out[t] : 0.0f;
    __syncthreads();
    float gm = 0.0f;
    #pragma unroll 8
    for (int g = 0; g < FDIM; g++) gm = fmaf(sB[g], g_W3T[g*FDIM + t], gm);
    g_gm[i*FDIM + t] = gm;
}

// ---------------------------------------------------------------------------
// K3: backward per pair -> dE/dq scatter. Block per atom i, 128 threads.
__global__ void __launch_bounds__(FDIM)
k_bwd(const float* __restrict__ q,
      const float* __restrict__ W1, const float* __restrict__ b1) {
    int i = blockIdx.x, t = threadIdx.x;
    __shared__ float srbf[NRBF];
    __shared__ float sgf[FDIM];
    __shared__ float sgz[FDIM];

    float qx = q[3*i], qy = q[3*i+1], qz = q[3*i+2];
    float gmf = g_gm[i*FDIM + t];
    float b1t = b1[t];
    float fx = 0.0f, fy = 0.0f, fz = 0.0f;   // dE/dq_i accumulator (lane 0 only)
    int cnt = g_cnt[i];

    for (int jn = 0; jn < cnt; jn++) {
        int j = g_nbr[i*MAXNBR + jn];
        float dx = qx - q[3*j], dy = qy - q[3*j+1], dz = qz - q[3*j+2];
        float d = sqrtf(dx*dx + dy*dy + dz*dz);

        __syncthreads();
        sgf[t] = gmf * g_h[j*FDIM + t];        // dE/dfilt
        if (t < NRBF) {
            float u = d - (float)t * CSPf;
            srbf[t] = __expf(-GAMf * u * u);
        }
        __syncthreads();

        // recompute z for the relu mask, then gz = 1[z>0] * (W2^T @ gfilt)
        float z = b1t;
        #pragma unroll
        for (int k = 0; k < NRBF; k++) z = fmaf(srbf[k], W1[k*FDIM + t], z);
        float gz = 0.0f;
        #pragma unroll 8
        for (int f = 0; f < FDIM; f++) gz = fmaf(sgf[f], g_W2T[f*FDIM + t], gz);
        sgz[t] = (z > 0.0f) ? gz : 0.0f;
        __syncthreads();

        if (t < NRBF) {                        // warp 0: grbf + dE/dd reduction
            float gr = 0.0f;
            #pragma unroll 8
            for (int f = 0; f < FDIM; f++) gr = fmaf(W1[t*FDIM + f], sgz[f], gr);
            float u = d - (float)t * CSPf;
            float term = gr * (-2.0f * GAMf * u) * srbf[t];   // dE/dd partial
            #pragma unroll
            for (int off = 16; off > 0; off >>= 1)
                term += __shfl_down_sync(0xffffffffu, term, off);
            if (t == 0) {
                float s = term / d;            // (dE/dd)/d
                float gx = s*dx, gy = s*dy, gzc = s*dz;
                fx += gx; fy += gy; fz += gzc;                 // dd/dq_i = +disp/d
                atomicAdd(&g_gq[3*j + 0], -gx);                // dd/dq_j = -disp/d
                atomicAdd(&g_gq[3*j + 1], -gy);
                atomicAdd(&g_gq[3*j + 2], -gzc);
            }
        }
    }
    if (t == 0) {
        atomicAdd(&g_gq[3*i + 0], fx);
        atomicAdd(&g_gq[3*i + 1], fy);
        atomicAdd(&g_gq[3*i + 2], fz);
    }
}

// ---------------------------------------------------------------------------
// K4: KE reduction + dvdt + v passthrough + Nose-Hoover chain RHS
__global__ void k_fin(const float* __restrict__ v, const float* __restrict__ mass,
                      const float* __restrict__ p_eta, float* __restrict__ out) {
    __shared__ float red[256];
    int t = threadIdx.x;
    float ke = 0.0f;
    for (int n = t; n < NA; n += 256) {
        float mn = mass[n];
        float v0 = v[3*n], v1 = v[3*n+1], v2 = v[3*n+2];
        ke += mn * (v0*v0 + v1*v1 + v2*v2);
    }
    red[t] = ke;
    __syncthreads();
    for (int off = 128; off > 0; off >>= 1) {
        if (t < off) red[t] += red[t + off];
        __syncthreads();
    }
    float pe0 = p_eta[0];
    for (int idx = t; idx < NA*3; idx += 256) {
        int n = idx / 3;
        float mn = mass[n], vv = v[idx];
        // f = -dE/dq ; coupled = p_eta0 * (m v) / Q0 ; dvdt = (f - coupled)/m
        out[idx]        = (-g_gq[idx] - pe0 * mn * vv / Q0f) / mn;
        out[NA*3 + idx] = vv;
    }
    if (t == 0) {
        float s_ke = 0.5f * red[0];
        float pe1 = p_eta[1], pe2 = p_eta[2], pe3 = p_eta[3];
        out[2*NA*3 + 0] = 2.0f*(s_ke - TARGETf) - pe0*pe1/QCf;
        out[2*NA*3 + 1] = pe0*pe0/Q0f - KTf - pe1*pe2/QCf;
        out[2*NA*3 + 2] = pe1*pe1/QCf - KTf - pe2*pe3/QCf;
        out[2*NA*3 + 3] = pe2*pe2/QCf - KTf;
    }
}

// ---------------------------------------------------------------------------
extern "C" void kernel_launch(void* const* d_in, const int* in_sizes, int n_in,
                              void* d_out, int out_size) {
    const float* v     = (const float*)d_in[0];
    const float* q     = (const float*)d_in[1];
    const float* p_eta = (const float*)d_in[2];
    const float* mass  = (const float*)d_in[3];
    const float* embed = (const float*)d_in[4];
    const float* W1    = (const float*)d_in[5];
    const float* b1    = (const float*)d_in[6];
    const float* W2    = (const float*)d_in[7];
    const float* b2    = (const float*)d_in[8];
    const float* W3    = (const float*)d_in[9];
    const float* w_out = (const float*)d_in[10];
    const int*   zat   = (const int*)d_in[11];
    float* out = (float*)d_out;
    (void)in_sizes; (void)n_in; (void)out_size;

    k_prep<<<NA, FDIM>>>(embed, zat, W2, W3);
    k_nbr <<<NA, 256 >>>(q);
    k_fwd <<<NA, FDIM>>>(q, W1, b1, W2, b2, W3, w_out);
    k_bwd <<<NA, FDIM>>>(q, W1, b1);
    k_fin <<<1,  256 >>>(v, mass, p_eta, out);
}

// round 9
// speedup vs baseline: 4.7365x; 4.7191x over previous
#include <cuda_runtime.h>
#include <math.h>

#define NA   768
#define FDIM 128
#define NRBF 32
#define MAXNBR 192

// Physics constants (match reference exactly)
#define CUT2f   25.0f
#define GAMf    40.96f                       /* (32/5)^2 */
#define CSPf    (5.0f/31.0f)                 /* RBF center spacing */
#define KBf     8.617330337217213e-05f
#define KTf     (300.0f*KBf)
#define Q0f     (2.0f*(float)(NA*3)*KTf*400.0f)
#define QCf     (2.0f*KTf*400.0f)
#define TARGETf (0.5f*(float)(NA*3)*KTf)

// Scratch (static __device__ arrays: allocation-free, graph-safe)
__device__ int   g_nbr[NA*MAXNBR];
__device__ int   g_cnt[NA];
__device__ float g_h  [NA*FDIM];
__device__ float g_W3T[FDIM*FDIM];
__device__ float g_gm [NA*FDIM];     // dE/dm per atom
__device__ float g_gq [NA*3];        // dE/dq accumulator

// group-scoped barrier: 128 threads, ids 1..2
__device__ __forceinline__ void barg(int id) {
    asm volatile("bar.sync %0, %1;" :: "r"(id), "r"(128) : "memory");
}

// ---------------------------------------------------------------------------
// K0: gather h = embed[atomic_numbers], transpose W3
__global__ void k_prep(const float* __restrict__ embed, const int* __restrict__ zat,
                       const float* __restrict__ W3) {
    int b = blockIdx.x, t = threadIdx.x;
    g_h[b*FDIM + t] = embed[zat[b]*FDIM + t];
    if (b < FDIM) g_W3T[b*FDIM + t] = W3[t*FDIM + b];
}

// ---------------------------------------------------------------------------
// K1: cutoff neighbor list (block per atom, q cached in smem) + zero forces
__global__ void k_nbr(const float* __restrict__ q) {
    __shared__ float sq[NA*3];
    __shared__ int cnt;
    int i = blockIdx.x, t = threadIdx.x;
    if (t == 0) cnt = 0;
    if (t < 3)  g_gq[i*3 + t] = 0.0f;
    for (int idx = t; idx < NA*3; idx += 256) sq[idx] = q[idx];
    __syncthreads();
    float qx = sq[3*i], qy = sq[3*i+1], qz = sq[3*i+2];
    for (int j = t; j < NA; j += 256) {
        if (j == i) continue;
        float dx = qx - sq[3*j], dy = qy - sq[3*j+1], dz = qz - sq[3*j+2];
        float d2 = dx*dx + dy*dy + dz*dz;
        if (d2 < CUT2f) {
            int p = atomicAdd(&cnt, 1);
            if (p < MAXNBR) g_nbr[i*MAXNBR + p] = j;
        }
    }
    __syncthreads();
    if (t == 0) g_cnt[i] = (cnt < MAXNBR) ? cnt : MAXNBR;
}

// ---------------------------------------------------------------------------
// K2: forward messages m_i + fused head dE/dm_i.
// Block = 256 threads = 2 independent groups of 128; 4 neighbors per group-iter.
// smem: sW2 padded [128][129] + per-group {rbf 4x32, sA 4x128} + sPart[256]
#define FWD_SMEM_FLOATS (FDIM*129 + 2*640 + 256)
__global__ void __launch_bounds__(256, 3)
k_fwd(const float* __restrict__ q,
      const float* __restrict__ W1, const float* __restrict__ b1,
      const float* __restrict__ W2, const float* __restrict__ b2,
      const float* __restrict__ W3, const float* __restrict__ w_out) {
    extern __shared__ float sm[];
    float* sW2 = sm;                                  // 128*129
    int i = blockIdx.x, t = threadIdx.x;
    int g = t >> 7, lt = t & 127;
    float* grp   = sm + FDIM*129 + g*640;
    float* rbf   = grp;                               // 4*32
    float* sA    = grp + 128;                         // 4*128
    float* sPart = sm + FDIM*129 + 1280;              // 256

    for (int idx = t; idx < FDIM*FDIM; idx += 256)
        sW2[(idx>>7)*129 + (idx&127)] = W2[idx];

    float qx = q[3*i], qy = q[3*i+1], qz = q[3*i+2];
    float b1t = b1[lt], b2t = b2[lt];
    float m = 0.0f;
    int cnt = g_cnt[i];
    __syncthreads();

    for (int base = g*4; base < cnt; base += 8) {
        int jv[4]; bool val[4];
        #pragma unroll
        for (int n = 0; n < 4; n++) {
            int jn = base + n;
            val[n] = jn < cnt;
            jv[n]  = val[n] ? g_nbr[i*MAXNBR + jn] : i;
        }
        barg(g+1);
        {   // 128 threads: n = lt>>5 neighbor, k = lt&31 rbf index
            int n = lt >> 5, k = lt & 31;
            int j = jv[n];
            float dx = qx - q[3*j], dy = qy - q[3*j+1], dz = qz - q[3*j+2];
            float d = val[n] ? sqrtf(dx*dx + dy*dy + dz*dz) : 1.0f;
            float u = d - (float)k * CSPf;
            rbf[lt] = __expf(-GAMf * u * u);
        }
        barg(g+1);
        // z_n = b1 + rbf_n @ W1  (W1 value reused across 4 neighbors)
        float z0=b1t, z1=b1t, z2=b1t, z3=b1t;
        #pragma unroll
        for (int k4 = 0; k4 < NRBF; k4 += 4) {
            float4 r0 = *(const float4*)&rbf[0*32+k4];
            float4 r1 = *(const float4*)&rbf[1*32+k4];
            float4 r2 = *(const float4*)&rbf[2*32+k4];
            float4 r3 = *(const float4*)&rbf[3*32+k4];
            #pragma unroll
            for (int e = 0; e < 4; e++) {
                float w = W1[(k4+e)*FDIM + lt];
                z0 = fmaf((&r0.x)[e], w, z0);
                z1 = fmaf((&r1.x)[e], w, z1);
                z2 = fmaf((&r2.x)[e], w, z2);
                z3 = fmaf((&r3.x)[e], w, z3);
            }
        }
        sA[0*128+lt] = fmaxf(z0, 0.0f);
        sA[1*128+lt] = fmaxf(z1, 0.0f);
        sA[2*128+lt] = fmaxf(z2, 0.0f);
        sA[3*128+lt] = fmaxf(z3, 0.0f);
        barg(g+1);
        // filt_n = b2 + A_n @ W2  (sW2 value reused across 4 neighbors)
        float f0=b2t, f1=b2t, f2=b2t, f3=b2t;
        #pragma unroll 8
        for (int f4 = 0; f4 < FDIM; f4 += 4) {
            float4 a0 = *(const float4*)&sA[0*128+f4];
            float4 a1 = *(const float4*)&sA[1*128+f4];
            float4 a2 = *(const float4*)&sA[2*128+f4];
            float4 a3 = *(const float4*)&sA[3*128+f4];
            #pragma unroll
            for (int e = 0; e < 4; e++) {
                float w = sW2[(f4+e)*129 + lt];
                f0 = fmaf((&a0.x)[e], w, f0);
                f1 = fmaf((&a1.x)[e], w, f1);
                f2 = fmaf((&a2.x)[e], w, f2);
                f3 = fmaf((&a3.x)[e], w, f3);
            }
        }
        if (val[0]) m = fmaf(f0, g_h[jv[0]*FDIM + lt], m);
        if (val[1]) m = fmaf(f1, g_h[jv[1]*FDIM + lt], m);
        if (val[2]) m = fmaf(f2, g_h[jv[2]*FDIM + lt], m);
        if (val[3]) m = fmaf(f3, g_h[jv[3]*FDIM + lt], m);
    }

    // combine group partials, then head: a = m@W3 ; gm = W3 @ (w_out * 1[a>0])
    __syncthreads();
    sPart[t] = m;
    __syncthreads();
    if (g == 0) {
        float mt = sPart[lt] + sPart[128 + lt];
        float* sM = sA;           // group-0 scratch reuse
        float* sB = sA + 128;
        sM[lt] = mt;
        barg(1);
        float a = 0.0f;
        #pragma unroll 8
        for (int f = 0; f < FDIM; f++) a = fmaf(sM[f], W3[f*FDIM + lt], a);
        sB[lt] = (a > 0.0f) ? w_out[lt] : 0.0f;
        barg(1);
        float gm = 0.0f;
        #pragma unroll 8
        for (int f = 0; f < FDIM; f++) gm = fmaf(sB[f], g_W3T[f*FDIM + lt], gm);
        g_gm[i*FDIM + lt] = gm;
    }
}

// ---------------------------------------------------------------------------
// K3: backward per pair -> dE/dq scatter.
// Same structure: 2 groups x 4 neighbors; dE/dd distributed over all threads:
//   dE/dd = sum_t gz_t * (W1^T @ crbf)_t ,  crbf_k = -2*gamma*(d-c_k)*rbf_k
// smem: sW2 [128][129] + per-group {rbf 128, crbf 128, sgf 512, sRed 16, sD 16}
#define BWD_SMEM_FLOATS (FDIM*129 + 2*800)
__global__ void __launch_bounds__(256, 3)
k_bwd(const float* __restrict__ q,
      const float* __restrict__ W1, const float* __restrict__ b1,
      const float* __restrict__ W2) {
    extern __shared__ float sm[];
    float* sW2 = sm;
    int i = blockIdx.x, t = threadIdx.x;
    int g = t >> 7, lt = t & 127, warp = lt >> 5, lane = t & 31;
    float* grp  = sm + FDIM*129 + g*800;
    float* rbf  = grp;          // 4*32
    float* crbf = grp + 128;    // 4*32
    float* sgf  = grp + 256;    // 4*128
    float* sRed = grp + 768;    // 16
    float* sD   = grp + 784;    // 16: {dx,dy,dz,d} per neighbor lane

    for (int idx = t; idx < FDIM*FDIM; idx += 256)
        sW2[(idx>>7)*129 + (idx&127)] = W2[idx];

    float qx = q[3*i], qy = q[3*i+1], qz = q[3*i+2];
    float gmf = g_gm[i*FDIM + lt];
    float b1t = b1[lt];
    int cnt = g_cnt[i];
    __syncthreads();

    for (int base = g*4; base < cnt; base += 8) {
        int jv[4]; bool val[4];
        #pragma unroll
        for (int n = 0; n < 4; n++) {
            int jn = base + n;
            val[n] = jn < cnt;
            jv[n]  = val[n] ? g_nbr[i*MAXNBR + jn] : i;
        }
        barg(g+1);
        {
            int n = lt >> 5, k = lt & 31;
            int j = jv[n];
            float dx = qx - q[3*j], dy = qy - q[3*j+1], dz = qz - q[3*j+2];
            float d = val[n] ? sqrtf(dx*dx + dy*dy + dz*dz) : 1.0f;
            float u = d - (float)k * CSPf;
            float e = __expf(-GAMf * u * u);
            rbf[lt]  = e;
            crbf[lt] = -2.0f * GAMf * u * e;
            if (k == 0) { sD[n*4+0]=dx; sD[n*4+1]=dy; sD[n*4+2]=dz; sD[n*4+3]=d; }
        }
        #pragma unroll
        for (int n = 0; n < 4; n++)
            sgf[n*128 + lt] = val[n] ? gmf * g_h[jv[n]*FDIM + lt] : 0.0f;
        barg(g+1);
        // recompute z (relu mask) and acc = (W1^T @ crbf)_lt, per neighbor
        float z0=b1t, z1=b1t, z2=b1t, z3=b1t;
        float c0=0.f, c1=0.f, c2=0.f, c3=0.f;
        #pragma unroll
        for (int k4 = 0; k4 < NRBF; k4 += 4) {
            float4 r0 = *(const float4*)&rbf[0*32+k4];
            float4 r1 = *(const float4*)&rbf[1*32+k4];
            float4 r2 = *(const float4*)&rbf[2*32+k4];
            float4 r3 = *(const float4*)&rbf[3*32+k4];
            float4 q0 = *(const float4*)&crbf[0*32+k4];
            float4 q1 = *(const float4*)&crbf[1*32+k4];
            float4 q2 = *(const float4*)&crbf[2*32+k4];
            float4 q3 = *(const float4*)&crbf[3*32+k4];
            #pragma unroll
            for (int e = 0; e < 4; e++) {
                float w = W1[(k4+e)*FDIM + lt];
                z0 = fmaf((&r0.x)[e], w, z0);  c0 = fmaf((&q0.x)[e], w, c0);
                z1 = fmaf((&r1.x)[e], w, z1);  c1 = fmaf((&q1.x)[e], w, c1);
                z2 = fmaf((&r2.x)[e], w, z2);  c2 = fmaf((&q2.x)[e], w, c2);
                z3 = fmaf((&r3.x)[e], w, z3);  c3 = fmaf((&q3.x)[e], w, c3);
            }
        }
        // gz_n = (W2^T @ gfilt_n)_lt  -- row read of padded sW2, conflict-free
        float gz0=0.f, gz1=0.f, gz2=0.f, gz3=0.f;
        #pragma unroll 8
        for (int f4 = 0; f4 < FDIM; f4 += 4) {
            float4 a0 = *(const float4*)&sgf[0*128+f4];
            float4 a1 = *(const float4*)&sgf[1*128+f4];
            float4 a2 = *(const float4*)&sgf[2*128+f4];
            float4 a3 = *(const float4*)&sgf[3*128+f4];
            #pragma unroll
            for (int e = 0; e < 4; e++) {
                float w = sW2[lt*129 + f4 + e];
                gz0 = fmaf((&a0.x)[e], w, gz0);
                gz1 = fmaf((&a1.x)[e], w, gz1);
                gz2 = fmaf((&a2.x)[e], w, gz2);
                gz3 = fmaf((&a3.x)[e], w, gz3);
            }
        }
        float p0 = (z0 > 0.f ? gz0 : 0.f) * c0;
        float p1 = (z1 > 0.f ? gz1 : 0.f) * c1;
        float p2 = (z2 > 0.f ? gz2 : 0.f) * c2;
        float p3 = (z3 > 0.f ? gz3 : 0.f) * c3;
        #pragma unroll
        for (int off = 16; off > 0; off >>= 1) {
            p0 += __shfl_down_sync(0xffffffffu, p0, off);
            p1 += __shfl_down_sync(0xffffffffu, p1, off);
            p2 += __shfl_down_sync(0xffffffffu, p2, off);
            p3 += __shfl_down_sync(0xffffffffu, p3, off);
        }
        if (lane == 0) {
            sRed[0*4+warp] = p0; sRed[1*4+warp] = p1;
            sRed[2*4+warp] = p2; sRed[3*4+warp] = p3;
        }
        barg(g+1);
        if (lt < 4 && (base + lt) < cnt) {
            int n = lt;
            float s = (sRed[n*4+0] + sRed[n*4+1] + sRed[n*4+2] + sRed[n*4+3]) / sD[n*4+3];
            float gx = s*sD[n*4+0], gy = s*sD[n*4+1], gzc = s*sD[n*4+2];
            atomicAdd(&g_gq[3*i+0],  gx);
            atomicAdd(&g_gq[3*i+1],  gy);
            atomicAdd(&g_gq[3*i+2],  gzc);
            int j = jv[n];
            atomicAdd(&g_gq[3*j+0], -gx);
            atomicAdd(&g_gq[3*j+1], -gy);
            atomicAdd(&g_gq[3*j+2], -gzc);
        }
    }
}

// ---------------------------------------------------------------------------
// K4: KE reduction + dvdt + v passthrough + Nose-Hoover chain RHS
__global__ void k_fin(const float* __restrict__ v, const float* __restrict__ mass,
                      const float* __restrict__ p_eta, float* __restrict__ out) {
    __shared__ float red[256];
    int t = threadIdx.x;
    float ke = 0.0f;
    for (int n = t; n < NA; n += 256) {
        float mn = mass[n];
        float v0 = v[3*n], v1 = v[3*n+1], v2 = v[3*n+2];
        ke += mn * (v0*v0 + v1*v1 + v2*v2);
    }
    red[t] = ke;
    __syncthreads();
    for (int off = 128; off > 0; off >>= 1) {
        if (t < off) red[t] += red[t + off];
        __syncthreads();
    }
    float pe0 = p_eta[0];
    for (int idx = t; idx < NA*3; idx += 256) {
        int n = idx / 3;
        float mn = mass[n], vv = v[idx];
        out[idx]        = (-g_gq[idx] - pe0 * mn * vv / Q0f) / mn;
        out[NA*3 + idx] = vv;
    }
    if (t == 0) {
        float s_ke = 0.5f * red[0];
        float pe1 = p_eta[1], pe2 = p_eta[2], pe3 = p_eta[3];
        out[2*NA*3 + 0] = 2.0f*(s_ke - TARGETf) - pe0*pe1/QCf;
        out[2*NA*3 + 1] = pe0*pe0/Q0f - KTf - pe1*pe2/QCf;
        out[2*NA*3 + 2] = pe1*pe1/QCf - KTf - pe2*pe3/QCf;
        out[2*NA*3 + 3] = pe2*pe2/QCf - KTf;
    }
}

// ---------------------------------------------------------------------------
extern "C" void kernel_launch(void* const* d_in, const int* in_sizes, int n_in,
                              void* d_out, int out_size) {
    const float* v     = (const float*)d_in[0];
    const float* q     = (const float*)d_in[1];
    const float* p_eta = (const float*)d_in[2];
    const float* mass  = (const float*)d_in[3];
    const float* embed = (const float*)d_in[4];
    const float* W1    = (const float*)d_in[5];
    const float* b1    = (const float*)d_in[6];
    const float* W2    = (const float*)d_in[7];
    const float* b2    = (const float*)d_in[8];
    const float* W3    = (const float*)d_in[9];
    const float* w_out = (const float*)d_in[10];
    const int*   zat   = (const int*)d_in[11];
    float* out = (float*)d_out;
    (void)in_sizes; (void)n_in; (void)out_size;

    const int fwd_smem = FWD_SMEM_FLOATS * (int)sizeof(float);   // ~70.5 KB
    const int bwd_smem = BWD_SMEM_FLOATS * (int)sizeof(float);   // ~70.8 KB
    cudaFuncSetAttribute(k_fwd, cudaFuncAttributeMaxDynamicSharedMemorySize, fwd_smem);
    cudaFuncSetAttribute(k_bwd, cudaFuncAttributeMaxDynamicSharedMemorySize, bwd_smem);

    k_prep<<<NA, FDIM>>>(embed, zat, W3);
    k_nbr <<<NA, 256 >>>(q);
    k_fwd <<<NA, 256, fwd_smem>>>(q, W1, b1, W2, b2, W3, w_out);
    k_bwd <<<NA, 256, bwd_smem>>>(q, W1, b1, W2);
    k_fin <<<1,  256 >>>(v, mass, p_eta, out);
}